// round 13
// baseline (speedup 1.0000x reference)
#include <cuda_runtime.h>

// YOLO loss, sm_103a — round 12: explicit load batching (MLP=10) + 8 slices.
// float4 p[10] staged before any use forces ptxas to front-batch all 10
// LDG.128s (regs ~64), turning per-warp serial L2 latency into one exposure.

#define S_GRID   26
#define NCH      255
#define CELLS    676
#define Q4       169               // CELLS/4
#define BATCH_N  128
#define T_TGT    50
#define L_COORD  5.0f
#define L_NOOBJ  0.5f

#define CSPLIT   8                 // class-channel slices per image (10 ch each)
#define TPB      192
#define NBLOCKS  (BATCH_N * CSPLIT)    // 1024

__device__ float    g_acc = 0.0f;      // reset by last block each call
__device__ unsigned g_cnt = 0u;

__global__ __launch_bounds__(TPB)
void yolo_loss_kernel(const float* __restrict__ pred,
                      const float* __restrict__ tgt,
                      float* __restrict__ out)
{
    const int tid = threadIdx.x;
    const int b   = blockIdx.x >> 3;       // image
    const int r   = blockIdx.x & 7;        // slice (0..7)

    __shared__ float s_n[CELLS];
    __shared__ float s_warp[TPB / 32];

    const float* pb  = pred + (size_t)b * NCH * CELLS;
    const float* tgb = tgt  + (size_t)b * T_TGT * 5;

    float sum = 0.0f;

    // ============ EARLY ISSUE: batched stream loads (forced MLP=10) =========
    float4 p[10];
    float4 cp0 = make_float4(0.f, 0.f, 0.f, 0.f);
    if (tid < Q4) {
        const int j = tid;
        const float4* base = (const float4*)(pb + (size_t)(5 + 10 * r) * CELLS) + j;
        #pragma unroll
        for (int k = 0; k < 10; k++) p[k] = __ldg(base + k * Q4);   // front-batched
        if (r == 0) cp0 = __ldg((const float4*)pb + j);             // conf0 (masked later)
        else if (r == 1) {                                          // conf box 1 (ch 85)
            const float4 c = __ldg((const float4*)(pb + (size_t)85 * CELLS) + j);
            sum += L_NOOBJ * (c.x*c.x + c.y*c.y + c.z*c.z + c.w*c.w);
        } else if (r == 2) {                                        // conf box 2 (ch 170)
            const float4 c = __ldg((const float4*)(pb + (size_t)170 * CELLS) + j);
            sum += L_NOOBJ * (c.x*c.x + c.y*c.y + c.z*c.z + c.w*c.w);
        }
    }

    // target data (phase-A scatter for all slices; gather duty on slice 3)
    float clsf = 0.f, cx = 2.f, cy = 2.f, tw = 0.f, th = 0.f;   // cx=2 -> invalid
    if (tid < T_TGT) {
        clsf = __ldg(tgb + tid * 5 + 0);
        cx   = __ldg(tgb + tid * 5 + 1);
        cy   = __ldg(tgb + tid * 5 + 2);
        tw   = __ldg(tgb + tid * 5 + 3);
        th   = __ldg(tgb + tid * 5 + 4);
    }
    const int gx = (int)(cx * S_GRID);          // trunc == floor (cx >= 0)
    const int gy = (int)(cy * S_GRID);
    const bool tvalid = (tid < T_TGT) && (gx < S_GRID) && (gy < S_GRID);
    const int cell = min(max(gy,0),S_GRID-1) * S_GRID + min(max(gx,0),S_GRID-1);

    if (r == 3 && tvalid) {                     // per-target gather: coord + cls
        const float* cpp = pb + cell;
        const int clsi = (int)clsf;
        const float q1 = __ldg(cpp + (size_t)1 * CELLS);
        const float q2 = __ldg(cpp + (size_t)2 * CELLS);
        const float q3 = __ldg(cpp + (size_t)3 * CELLS);
        const float q4 = __ldg(cpp + (size_t)4 * CELLS);
        const float pg = __ldg(cpp + (size_t)(5 + clsi) * CELLS);
        const float d1 = q1 - cx, d2 = q2 - cy, d3 = q3 - tw, d4 = q4 - th;
        sum += L_COORD * (d1*d1 + d2*d2 + d3*d3 + d4*d4) + 1.0f - 2.0f * pg;
    }

    // ============ PHASE A: per-cell count n (overlapped with loads) =========
    for (int i = tid; i < CELLS; i += TPB) s_n[i] = 0.0f;
    __syncthreads();
    if (tvalid) atomicAdd(&s_n[cell], 1.0f);
    __syncthreads();

    // ============ COMBINE: Σp² then apply n ================================
    if (tid < Q4) {
        float4 s = make_float4(0.f, 0.f, 0.f, 0.f);
        #pragma unroll
        for (int k = 0; k < 10; k++) {
            s.x = fmaf(p[k].x, p[k].x, s.x);
            s.y = fmaf(p[k].y, p[k].y, s.y);
            s.z = fmaf(p[k].z, p[k].z, s.z);
            s.w = fmaf(p[k].w, p[k].w, s.w);
        }
        const float4 nv = *(const float4*)&s_n[4 * tid];
        sum += nv.x * s.x + nv.y * s.y + nv.z * s.z + nv.w * s.w;
        if (r == 0) {
            float t = 0.f;
            t += (nv.x == 0.f) ? cp0.x * cp0.x : 0.f;
            t += (nv.y == 0.f) ? cp0.y * cp0.y : 0.f;
            t += (nv.z == 0.f) ? cp0.z * cp0.z : 0.f;
            t += (nv.w == 0.f) ? cp0.w * cp0.w : 0.f;
            sum += L_NOOBJ * t;
        }
    }

    // ---- block reduce + last-block-done finalization (single launch) ----
    const int lane = tid & 31;
    const int warp = tid >> 5;
    #pragma unroll
    for (int off = 16; off; off >>= 1)
        sum += __shfl_down_sync(0xffffffffu, sum, off);
    if (lane == 0) s_warp[warp] = sum;
    __syncthreads();
    if (tid == 0) {
        float v = s_warp[0];
        #pragma unroll
        for (int w = 1; w < TPB / 32; w++) v += s_warp[w];
        atomicAdd(&g_acc, v);
        __threadfence();
        const unsigned ticket = atomicAdd(&g_cnt, 1u);
        if (ticket == NBLOCKS - 1) {
            const float total = atomicAdd(&g_acc, 0.0f);   // coherent read
            out[0] = total * (1.0f / BATCH_N);
            g_acc = 0.0f;                                  // replay-safe reset
            g_cnt = 0u;
        }
    }
}

extern "C" void kernel_launch(void* const* d_in, const int* in_sizes, int n_in,
                              void* d_out, int out_size)
{
    const float* pred = (const float*)d_in[0];
    const float* tgt  = (const float*)d_in[1];
    float* out = (float*)d_out;

    yolo_loss_kernel<<<NBLOCKS, TPB>>>(pred, tgt, out);
}

// round 14
// speedup vs baseline: 1.2316x; 1.2316x over previous
#include <cuda_runtime.h>

// YOLO loss, sm_103a — round 13: R11 structure (CSPLIT=4, 512 blocks, overlap)
// + R12 explicit batching as 2 sequential batches of 10 (regs~64, 2 exposures).

#define S_GRID   26
#define NCH      255
#define CELLS    676
#define Q4       169               // CELLS/4
#define BATCH_N  128
#define T_TGT    50
#define L_COORD  5.0f
#define L_NOOBJ  0.5f

#define CSPLIT   4                 // class-channel slices per image (20 ch each)
#define TPB      192
#define NBLOCKS  (BATCH_N * CSPLIT)    // 512

__device__ float    g_acc = 0.0f;      // reset by last block each call
__device__ unsigned g_cnt = 0u;

__global__ __launch_bounds__(TPB)
void yolo_loss_kernel(const float* __restrict__ pred,
                      const float* __restrict__ tgt,
                      float* __restrict__ out)
{
    const int tid = threadIdx.x;
    const int b   = blockIdx.x >> 2;       // image
    const int r   = blockIdx.x & 3;        // slice (0..3)

    __shared__ float s_n[CELLS];
    __shared__ float s_warp[TPB / 32];

    const float* pb  = pred + (size_t)b * NCH * CELLS;
    const float* tgb = tgt  + (size_t)b * T_TGT * 5;

    float sum = 0.0f;
    float4 s = make_float4(0.f, 0.f, 0.f, 0.f);
    float4 cp0 = make_float4(0.f, 0.f, 0.f, 0.f);

    // ===== EARLY ISSUE: stream loads, 2 batches of 10 (forced MLP=10) =======
    if (tid < Q4) {
        const int j = tid;
        const float4* base = (const float4*)(pb + (size_t)(5 + 20 * r) * CELLS) + j;

        if (r == 0) cp0 = __ldg((const float4*)pb + j);             // conf0
        else if (r == 1) {                                          // conf box1
            const float4 c = __ldg((const float4*)(pb + (size_t)85 * CELLS) + j);
            sum += L_NOOBJ * (c.x*c.x + c.y*c.y + c.z*c.z + c.w*c.w);
        } else if (r == 2) {                                        // conf box2
            const float4 c = __ldg((const float4*)(pb + (size_t)170 * CELLS) + j);
            sum += L_NOOBJ * (c.x*c.x + c.y*c.y + c.z*c.z + c.w*c.w);
        }

        float4 pA[10];
        #pragma unroll
        for (int k = 0; k < 10; k++) pA[k] = __ldg(base + k * Q4);  // batch 0
        #pragma unroll
        for (int k = 0; k < 10; k++) {
            s.x = fmaf(pA[k].x, pA[k].x, s.x);
            s.y = fmaf(pA[k].y, pA[k].y, s.y);
            s.z = fmaf(pA[k].z, pA[k].z, s.z);
            s.w = fmaf(pA[k].w, pA[k].w, s.w);
        }
        float4 pB[10];
        #pragma unroll
        for (int k = 0; k < 10; k++) pB[k] = __ldg(base + (10 + k) * Q4);  // batch 1
        #pragma unroll
        for (int k = 0; k < 10; k++) {
            s.x = fmaf(pB[k].x, pB[k].x, s.x);
            s.y = fmaf(pB[k].y, pB[k].y, s.y);
            s.z = fmaf(pB[k].z, pB[k].z, s.z);
            s.w = fmaf(pB[k].w, pB[k].w, s.w);
        }
    }

    // target data (phase-A scatter for all slices; gather duty on slice 3)
    float clsf = 0.f, cx = 2.f, cy = 2.f, tw = 0.f, th = 0.f;   // cx=2 -> invalid
    if (tid < T_TGT) {
        clsf = __ldg(tgb + tid * 5 + 0);
        cx   = __ldg(tgb + tid * 5 + 1);
        cy   = __ldg(tgb + tid * 5 + 2);
        tw   = __ldg(tgb + tid * 5 + 3);
        th   = __ldg(tgb + tid * 5 + 4);
    }
    const int gx = (int)(cx * S_GRID);          // trunc == floor (cx >= 0)
    const int gy = (int)(cy * S_GRID);
    const bool tvalid = (tid < T_TGT) && (gx < S_GRID) && (gy < S_GRID);
    const int cell = min(max(gy,0),S_GRID-1) * S_GRID + min(max(gx,0),S_GRID-1);

    if (r == 3 && tvalid) {                     // per-target gather: coord + cls
        const float* cpp = pb + cell;
        const int clsi = (int)clsf;
        const float q1 = __ldg(cpp + (size_t)1 * CELLS);
        const float q2 = __ldg(cpp + (size_t)2 * CELLS);
        const float q3 = __ldg(cpp + (size_t)3 * CELLS);
        const float q4 = __ldg(cpp + (size_t)4 * CELLS);
        const float pg = __ldg(cpp + (size_t)(5 + clsi) * CELLS);
        const float d1 = q1 - cx, d2 = q2 - cy, d3 = q3 - tw, d4 = q4 - th;
        sum += L_COORD * (d1*d1 + d2*d2 + d3*d3 + d4*d4) + 1.0f - 2.0f * pg;
    }

    // ===== PHASE A: per-cell count n (overlapped with in-flight loads) ======
    for (int i = tid; i < CELLS; i += TPB) s_n[i] = 0.0f;
    __syncthreads();
    if (tvalid) atomicAdd(&s_n[cell], 1.0f);
    __syncthreads();

    // ===== COMBINE: apply n to streamed sums ================================
    if (tid < Q4) {
        const float4 nv = *(const float4*)&s_n[4 * tid];
        sum += nv.x * s.x + nv.y * s.y + nv.z * s.z + nv.w * s.w;
        if (r == 0) {
            float t = 0.f;
            t += (nv.x == 0.f) ? cp0.x * cp0.x : 0.f;
            t += (nv.y == 0.f) ? cp0.y * cp0.y : 0.f;
            t += (nv.z == 0.f) ? cp0.z * cp0.z : 0.f;
            t += (nv.w == 0.f) ? cp0.w * cp0.w : 0.f;
            sum += L_NOOBJ * t;
        }
    }

    // ---- block reduce + last-block-done finalization (single launch) ----
    const int lane = tid & 31;
    const int warp = tid >> 5;
    #pragma unroll
    for (int off = 16; off; off >>= 1)
        sum += __shfl_down_sync(0xffffffffu, sum, off);
    if (lane == 0) s_warp[warp] = sum;
    __syncthreads();
    if (tid == 0) {
        float v = s_warp[0];
        #pragma unroll
        for (int w = 1; w < TPB / 32; w++) v += s_warp[w];
        atomicAdd(&g_acc, v);
        __threadfence();
        const unsigned ticket = atomicAdd(&g_cnt, 1u);
        if (ticket == NBLOCKS - 1) {
            const float total = atomicAdd(&g_acc, 0.0f);   // coherent read
            out[0] = total * (1.0f / BATCH_N);
            g_acc = 0.0f;                                  // replay-safe reset
            g_cnt = 0u;
        }
    }
}

extern "C" void kernel_launch(void* const* d_in, const int* in_sizes, int n_in,
                              void* d_out, int out_size)
{
    const float* pred = (const float*)d_in[0];
    const float* tgt  = (const float*)d_in[1];
    float* out = (float*)d_out;

    yolo_loss_kernel<<<NBLOCKS, TPB>>>(pred, tgt, out);
}